// round 1
// baseline (speedup 1.0000x reference)
#include <cuda_runtime.h>

// Problem constants
#define BATCH 4096
#define DIM   2048
#define NK    8
#define H2    64

// GEMM tiling
#define BM 64
#define BN 64
#define BK 16

// ---------------- device scratch (no allocation allowed) ----------------
__device__ int   g_kidx[BATCH];
__device__ int   g_count[NK];
__device__ int   g_offset[NK];
__device__ int   g_cursor[NK];
__device__ int   g_perm[BATCH];
__device__ int   g_tile_start[NK];
__device__ int   g_total_tiles;
__device__ float g_t2[NK];

// ---------------- prep kernels ----------------
__global__ void k_zero_counts() {
    int t = threadIdx.x;
    if (t < NK) { g_count[t] = 0; }
}

__global__ void k_kidx(const float* __restrict__ intention) {
    int b = blockIdx.x * blockDim.x + threadIdx.x;
    if (b >= BATCH) return;
    int k = 0;
#pragma unroll
    for (int i = 0; i < NK; i++)
        if (intention[b * NK + i] > 0.5f) k = i;
    g_kidx[b] = k;
    atomicAdd(&g_count[k], 1);
}

__global__ void k_scan() {
    // single thread: prefix sums over 8 groups
    int off = 0, tiles = 0;
    for (int k = 0; k < NK; k++) {
        g_offset[k] = off;
        g_cursor[k] = off;
        g_tile_start[k] = tiles;
        tiles += (g_count[k] + BM - 1) / BM;
        off += g_count[k];
    }
    g_total_tiles = tiles;
}

__global__ void k_scatter() {
    int b = blockIdx.x * blockDim.x + threadIdx.x;
    if (b >= BATCH) return;
    int k = g_kidx[b];
    int pos = atomicAdd(&g_cursor[k], 1);
    g_perm[pos] = b;
}

// t2[k] = sum_h relu(W2[h,k] + b2[h]) * W3[DIM + h]
__global__ void k_t2(const float* __restrict__ W2, const float* __restrict__ b2,
                     const float* __restrict__ W3) {
    int k = threadIdx.x;
    if (k >= NK) return;
    float s = 0.f;
    for (int h = 0; h < H2; h++) {
        float v = W2[h * NK + k] + b2[h];
        s += fmaxf(v, 0.f) * W3[DIM + h];
    }
    g_t2[k] = s;
}

__global__ void k_init_out(float* __restrict__ out, const float* __restrict__ b3) {
    int b = blockIdx.x * blockDim.x + threadIdx.x;
    if (b >= BATCH) return;
    out[b] = b3[0] + g_t2[g_kidx[b]];
}

// ---------------- fused grouped GEMM + relu + W3 reduction ----------------
// For group k (samples with intention k), compute
//   acc[m][n] = x[row_m, :] . W1[(dbase+n)*8 + k, :]
// then per row: partial = sum_n relu(acc + b1[(dbase+n)*8+k]) * W3[dbase+n]
// atomicAdd into out[row_m].
__global__ __launch_bounds__(256, 2)
void gemm_fused(const float* __restrict__ x, const float* __restrict__ W1,
                const float* __restrict__ b1, const float* __restrict__ W3,
                float* __restrict__ out) {
    int ty = blockIdx.y;
    if (ty >= g_total_tiles) return;

    int k = 0;
#pragma unroll
    for (int i = 1; i < NK; i++)
        if (ty >= g_tile_start[i]) k = i;
    int row0  = g_offset[k] + (ty - g_tile_start[k]) * BM;
    int rend  = g_offset[k] + g_count[k];
    int dbase = blockIdx.x * BN;

    __shared__ float As[BK][BM];
    __shared__ float Bs[BK][BN];

    int t   = threadIdx.x;
    int tn  = t & 15;      // 0..15 -> n micro-tile
    int tm  = t >> 4;      // 0..15 -> m micro-tile
    int lrow = t >> 2;     // 0..63 loader row
    int lseg = t & 3;      // 0..3  loader 4-float segment

    int prow = row0 + lrow;
    int sample = (prow < rend) ? g_perm[prow] : -1;
    bool valid = (sample >= 0);
    const float4* xv = (const float4*)(x + (size_t)(valid ? sample : 0) * DIM);
    const float4* wv = (const float4*)(W1 + ((size_t)(dbase + lrow) * NK + k) * DIM);

    float acc[4][4];
#pragma unroll
    for (int i = 0; i < 4; i++)
#pragma unroll
        for (int j = 0; j < 4; j++) acc[i][j] = 0.f;

    for (int j0 = 0; j0 < DIM / 4; j0 += BK / 4) {
        float4 av = valid ? xv[j0 + lseg] : make_float4(0.f, 0.f, 0.f, 0.f);
        float4 bv = wv[j0 + lseg];
        __syncthreads();
        As[lseg * 4 + 0][lrow] = av.x;
        As[lseg * 4 + 1][lrow] = av.y;
        As[lseg * 4 + 2][lrow] = av.z;
        As[lseg * 4 + 3][lrow] = av.w;
        Bs[lseg * 4 + 0][lrow] = bv.x;
        Bs[lseg * 4 + 1][lrow] = bv.y;
        Bs[lseg * 4 + 2][lrow] = bv.z;
        Bs[lseg * 4 + 3][lrow] = bv.w;
        __syncthreads();
#pragma unroll
        for (int kk = 0; kk < BK; kk++) {
            float4 a = *(const float4*)&As[kk][tm * 4];
            float4 b = *(const float4*)&Bs[kk][tn * 4];
            float ar[4] = {a.x, a.y, a.z, a.w};
            float br[4] = {b.x, b.y, b.z, b.w};
#pragma unroll
            for (int i = 0; i < 4; i++)
#pragma unroll
                for (int j = 0; j < 4; j++)
                    acc[i][j] = fmaf(ar[i], br[j], acc[i][j]);
        }
    }

    // Epilogue: relu + W3 weighting + reduction over n, one atomic per row
#pragma unroll
    for (int i = 0; i < 4; i++) {
        int m  = tm * 4 + i;
        int pr = row0 + m;
        float s = 0.f;
#pragma unroll
        for (int j = 0; j < 4; j++) {
            int d = dbase + tn * 4 + j;
            float v = acc[i][j] + b1[(size_t)d * NK + k];
            s += fmaxf(v, 0.f) * W3[d];
        }
        // reduce across the 16 tn lanes (width-16 segments align with tm groups)
#pragma unroll
        for (int off = 8; off >= 1; off >>= 1)
            s += __shfl_xor_sync(0xFFFFFFFFu, s, off, 16);
        if (tn == 0 && pr < rend) {
            atomicAdd(&out[g_perm[pr]], s);
        }
    }
}

// ---------------- launch ----------------
extern "C" void kernel_launch(void* const* d_in, const int* in_sizes, int n_in,
                              void* d_out, int out_size) {
    const float* x         = (const float*)d_in[0];
    const float* intention = (const float*)d_in[1];
    const float* W1        = (const float*)d_in[2];
    const float* b1        = (const float*)d_in[3];
    const float* W2        = (const float*)d_in[4];
    const float* b2        = (const float*)d_in[5];
    const float* W3        = (const float*)d_in[6];
    const float* b3        = (const float*)d_in[7];
    float* out             = (float*)d_out;

    k_zero_counts<<<1, NK>>>();
    k_kidx<<<BATCH / 256, 256>>>(intention);
    k_scan<<<1, 1>>>();
    k_scatter<<<BATCH / 256, 256>>>();
    k_t2<<<1, NK>>>(W2, b2, W3);
    k_init_out<<<BATCH / 256, 256>>>(out, b3);

    // max tiles: sum ceil(cnt_k/64) <= 4096/64 + 8 = 72
    dim3 grid(DIM / BN, 72);
    gemm_fused<<<grid, 256>>>(x, W1, b1, W3, out);
}

// round 4
// speedup vs baseline: 2.7147x; 2.7147x over previous
#include <cuda_runtime.h>
#include <cstdint>

// ---------------- problem constants ----------------
#define BATCH 4096
#define DIM   2048
#define NK    8
#define H2    64

// ---------------- tiling ----------------
#define BM     128
#define BN     128
#define KC     32
#define NCHUNK (DIM / KC)        // 64
#define GX     (DIM / BN)        // 16 d-blocks
#define GY     40                // max m-tiles: sum ceil(cnt_k/128) <= 32+8

#define PITCH   40               // bf16 elements per smem row (32 + 8 pad)
#define PITCH_B 80               // bytes
#define TILE_B  (128 * PITCH_B)  // 10240 bytes per tile

// ---------------- device scratch ----------------
__device__ int g_perm[BATCH];
__device__ int g_tile_k[GY];
__device__ int g_tile_row0[GY];
__device__ int g_tile_rend[GY];
__device__ int g_ntiles;

// ---------------- PTX helpers ----------------
__device__ __forceinline__ uint32_t smem_u32(const void* p) {
    uint32_t a;
    asm("{ .reg .u64 t; cvta.to.shared.u64 t, %1; cvt.u32.u64 %0, t; }" : "=r"(a) : "l"(p));
    return a;
}

__device__ __forceinline__ void ldsm4(uint32_t* r, uint32_t addr) {
    asm volatile("ldmatrix.sync.aligned.m8n8.x4.shared.b16 {%0,%1,%2,%3}, [%4];"
                 : "=r"(r[0]), "=r"(r[1]), "=r"(r[2]), "=r"(r[3]) : "r"(addr));
}

__device__ __forceinline__ void mma_bf16(float* c, const uint32_t* a, const uint32_t* b) {
    asm volatile(
        "mma.sync.aligned.m16n8k16.row.col.f32.bf16.bf16.f32 "
        "{%0,%1,%2,%3}, {%4,%5,%6,%7}, {%8,%9}, {%0,%1,%2,%3};"
        : "+f"(c[0]), "+f"(c[1]), "+f"(c[2]), "+f"(c[3])
        : "r"(a[0]), "r"(a[1]), "r"(a[2]), "r"(a[3]), "r"(b[0]), "r"(b[1]));
}

__device__ __forceinline__ void sts128(uint32_t addr, uint4 v) {
    asm volatile("st.shared.v4.b32 [%0], {%1,%2,%3,%4};"
                 :: "r"(addr), "r"(v.x), "r"(v.y), "r"(v.z), "r"(v.w) : "memory");
}

// pack two fp32 -> bf16x2 (lo_ -> lower half)
__device__ __forceinline__ uint32_t pk_bf16x2(float lo_, float hi_) {
    uint32_t r;
    asm("cvt.rn.bf16x2.f32 %0, %1, %2;" : "=r"(r) : "f"(hi_), "f"(lo_));
    return r;
}

// 8 fp32 -> hi uint4 (truncated top-16 bits) + lo uint4 (residual, rn-bf16)
__device__ __forceinline__ void cvt8(float4 a, float4 b, uint4& hi, uint4& lo) {
    uint32_t ua0 = __float_as_uint(a.x), ua1 = __float_as_uint(a.y);
    uint32_t ua2 = __float_as_uint(a.z), ua3 = __float_as_uint(a.w);
    uint32_t ub0 = __float_as_uint(b.x), ub1 = __float_as_uint(b.y);
    uint32_t ub2 = __float_as_uint(b.z), ub3 = __float_as_uint(b.w);
    hi.x = __byte_perm(ua0, ua1, 0x7632);
    hi.y = __byte_perm(ua2, ua3, 0x7632);
    hi.z = __byte_perm(ub0, ub1, 0x7632);
    hi.w = __byte_perm(ub2, ub3, 0x7632);
    float r0 = a.x - __uint_as_float(ua0 & 0xFFFF0000u);
    float r1 = a.y - __uint_as_float(ua1 & 0xFFFF0000u);
    float r2 = a.z - __uint_as_float(ua2 & 0xFFFF0000u);
    float r3 = a.w - __uint_as_float(ua3 & 0xFFFF0000u);
    float r4 = b.x - __uint_as_float(ub0 & 0xFFFF0000u);
    float r5 = b.y - __uint_as_float(ub1 & 0xFFFF0000u);
    float r6 = b.z - __uint_as_float(ub2 & 0xFFFF0000u);
    float r7 = b.w - __uint_as_float(ub3 & 0xFFFF0000u);
    lo.x = pk_bf16x2(r0, r1);
    lo.y = pk_bf16x2(r2, r3);
    lo.z = pk_bf16x2(r4, r5);
    lo.w = pk_bf16x2(r6, r7);
}

// ---------------- prep: sort by intention, tile table, t2, out init ----------------
__global__ void __launch_bounds__(1024) prep_kernel(
    const float* __restrict__ intention, const float* __restrict__ W2,
    const float* __restrict__ b2, const float* __restrict__ W3,
    const float* __restrict__ b3, float* __restrict__ out) {
    __shared__ int cnt[NK], cur[NK];
    __shared__ float t2s[NK];
    int t = threadIdx.x;
    if (t < NK) cnt[t] = 0;
    __syncthreads();

    int myk[4];
#pragma unroll
    for (int i = 0; i < 4; i++) {
        int b = t + i * 1024;
        const float4* p = (const float4*)(intention + (size_t)b * NK);
        float4 v0 = p[0], v1 = p[1];
        int k = 0;
        if (v0.y > 0.5f) k = 1;
        if (v0.z > 0.5f) k = 2;
        if (v0.w > 0.5f) k = 3;
        if (v1.x > 0.5f) k = 4;
        if (v1.y > 0.5f) k = 5;
        if (v1.z > 0.5f) k = 6;
        if (v1.w > 0.5f) k = 7;
        myk[i] = k;
        atomicAdd(&cnt[k], 1);
    }
    __syncthreads();

    if (t == 0) {
        int off = 0, nt = 0;
        for (int k = 0; k < NK; k++) {
            int c = cnt[k];
            for (int r = 0; r < c; r += BM) {
                g_tile_k[nt] = k;
                g_tile_row0[nt] = off + r;
                g_tile_rend[nt] = off + c;
                nt++;
            }
            cur[k] = off;
            off += c;
        }
        g_ntiles = nt;
    }
    if (t < NK) {
        float s = 0.f;
        for (int h = 0; h < H2; h++) {
            float v = W2[h * NK + t] + b2[h];
            s += fmaxf(v, 0.f) * W3[DIM + h];
        }
        t2s[t] = s;
    }
    __syncthreads();

    float bias = b3[0];
#pragma unroll
    for (int i = 0; i < 4; i++) {
        int b = t + i * 1024;
        int pos = atomicAdd(&cur[myk[i]], 1);
        g_perm[pos] = b;
        out[b] = bias + t2s[myk[i]];
    }
}

// ---------------- fused grouped HMMA GEMM ----------------
// blockIdx.x = m-tile (fast, so tiles sharing W1 run concurrently -> L2 reuse)
// blockIdx.y = d-block
__global__ void __launch_bounds__(256, 1) gemm_kernel(
    const float* __restrict__ x, const float* __restrict__ W1,
    const float* __restrict__ b1, const float* __restrict__ W3,
    float* __restrict__ out) {
    int tile = blockIdx.x;
    if (tile >= g_ntiles) return;
    int k     = g_tile_k[tile];
    int row0  = g_tile_row0[tile];
    int rend  = g_tile_rend[tile];
    int dbase = blockIdx.y * BN;

    __shared__ char smem[4 * TILE_B];   // Ahi | Alo | Bhi | Blo
    uint32_t sA_hi = smem_u32(smem);
    uint32_t sA_lo = sA_hi + TILE_B;
    uint32_t sB_hi = sA_hi + 2 * TILE_B;
    uint32_t sB_lo = sA_hi + 3 * TILE_B;

    int t    = threadIdx.x;
    int lane = t & 31;
    int wid  = t >> 5;
    int mw   = wid & 1;        // 2 warp-rows of 64
    int nw   = wid >> 1;       // 4 warp-cols of 32

    // ---- loader mapping: 2 threads per row, 16 fp32 each ----
    int lr  = t >> 1;          // 0..127
    int seg = t & 1;           // 0/1 (cols seg*16..+15)
    int pra = row0 + lr;
    int sampa = (pra < rend) ? g_perm[pra] : 0;
    const float* pa = x + (size_t)sampa * DIM + seg * 16;
    const float* pb = W1 + ((size_t)(dbase + lr) * NK + k) * DIM + seg * 16;
    uint32_t st_off = (uint32_t)lr * PITCH_B + (uint32_t)seg * 32u;

    // ---- ldmatrix lane base offsets ----
    int g = lane >> 3;         // 0..3 tile-slot
    // A x4: slots (mlo,klo)(mhi,klo)(mlo,khi)(mhi,khi)
    uint32_t a_row = (uint32_t)(mw * 64 + (lane & 7) + 8 * (g & 1));
    uint32_t a_off = a_row * PITCH_B + (uint32_t)(g >> 1) * 16u;
    // B x4: slots (n_j,klo)(n_j,khi)(n_j+8,klo)(n_j+8,khi)
    uint32_t b_row = (uint32_t)(nw * 32 + (lane & 7) + 8 * (g >> 1));
    uint32_t b_off = b_row * PITCH_B + (uint32_t)(g & 1) * 16u;

    float acc[4][4][4];
#pragma unroll
    for (int i = 0; i < 4; i++)
#pragma unroll
        for (int j = 0; j < 4; j++)
#pragma unroll
            for (int e = 0; e < 4; e++) acc[i][j][e] = 0.f;

    float4 a_st[4], b_st[4];
    // prologue: stage chunk 0
    {
        const float4* qa = (const float4*)pa;
        const float4* qb = (const float4*)pb;
#pragma unroll
        for (int i = 0; i < 4; i++) { a_st[i] = __ldg(qa + i); b_st[i] = __ldg(qb + i); }
    }

    for (int c = 0; c < NCHUNK; c++) {
        __syncthreads();   // previous compute done; buffer free
        // ---- convert + STS chunk c ----
        {
            uint4 h0, l0, h1, l1;
            cvt8(a_st[0], a_st[1], h0, l0);
            cvt8(a_st[2], a_st[3], h1, l1);
            sts128(sA_hi + st_off, h0);       sts128(sA_hi + st_off + 16, h1);
            sts128(sA_lo + st_off, l0);       sts128(sA_lo + st_off + 16, l1);
            cvt8(b_st[0], b_st[1], h0, l0);
            cvt8(b_st[2], b_st[3], h1, l1);
            sts128(sB_hi + st_off, h0);       sts128(sB_hi + st_off + 16, h1);
            sts128(sB_lo + st_off, l0);       sts128(sB_lo + st_off + 16, l1);
        }
        __syncthreads();
        // ---- stage chunk c+1 (latency hidden under compute) ----
        if (c + 1 < NCHUNK) {
            const float4* qa = (const float4*)(pa + (c + 1) * KC);
            const float4* qb = (const float4*)(pb + (c + 1) * KC);
#pragma unroll
            for (int i = 0; i < 4; i++) { a_st[i] = __ldg(qa + i); b_st[i] = __ldg(qb + i); }
        }
        // ---- compute chunk c: 2 k-steps x 3 split-products ----
#pragma unroll
        for (int ks = 0; ks < 2; ks++) {
            uint32_t koff = (uint32_t)ks * 32u;   // 16 bf16 = 32 bytes per k-step
            uint32_t Ahi[4][4], Alo[4][4], Bhi[2][4], Blo[2][4];
#pragma unroll
            for (int i = 0; i < 4; i++) {
                ldsm4(Ahi[i], sA_hi + a_off + (uint32_t)i * (16u * PITCH_B) + koff);
                ldsm4(Alo[i], sA_lo + a_off + (uint32_t)i * (16u * PITCH_B) + koff);
            }
#pragma unroll
            for (int jp = 0; jp < 2; jp++) {
                ldsm4(Bhi[jp], sB_hi + b_off + (uint32_t)jp * (16u * PITCH_B) + koff);
                ldsm4(Blo[jp], sB_lo + b_off + (uint32_t)jp * (16u * PITCH_B) + koff);
            }
#pragma unroll
            for (int i = 0; i < 4; i++)
#pragma unroll
                for (int j = 0; j < 4; j++) {
                    mma_bf16(acc[i][j], Ahi[i], &Bhi[j >> 1][(j & 1) * 2]);
                    mma_bf16(acc[i][j], Alo[i], &Bhi[j >> 1][(j & 1) * 2]);
                    mma_bf16(acc[i][j], Ahi[i], &Blo[j >> 1][(j & 1) * 2]);
                }
        }
    }

    // ---- fused epilogue: relu(acc + b1) * W3, row-reduce, atomicAdd ----
    float b1a[4], b1b[4], w3a[4], w3b[4];
#pragma unroll
    for (int j = 0; j < 4; j++) {
        int d = dbase + nw * 32 + j * 8 + 2 * (lane & 3);
        b1a[j] = __ldg(&b1[(size_t)d * NK + k]);
        b1b[j] = __ldg(&b1[(size_t)(d + 1) * NK + k]);
        w3a[j] = __ldg(&W3[d]);
        w3b[j] = __ldg(&W3[d + 1]);
    }
#pragma unroll
    for (int i = 0; i < 4; i++) {
        float s0 = 0.f, s1 = 0.f;
#pragma unroll
        for (int j = 0; j < 4; j++) {
            s0 = fmaf(fmaxf(acc[i][j][0] + b1a[j], 0.f), w3a[j], s0);
            s0 = fmaf(fmaxf(acc[i][j][1] + b1b[j], 0.f), w3b[j], s0);
            s1 = fmaf(fmaxf(acc[i][j][2] + b1a[j], 0.f), w3a[j], s1);
            s1 = fmaf(fmaxf(acc[i][j][3] + b1b[j], 0.f), w3b[j], s1);
        }
        s0 += __shfl_xor_sync(0xFFFFFFFFu, s0, 1);
        s0 += __shfl_xor_sync(0xFFFFFFFFu, s0, 2);
        s1 += __shfl_xor_sync(0xFFFFFFFFu, s1, 1);
        s1 += __shfl_xor_sync(0xFFFFFFFFu, s1, 2);
        if ((lane & 3) == 0) {
            int m0 = mw * 64 + i * 16 + (lane >> 2);
            int pr0 = row0 + m0;
            int pr1 = pr0 + 8;
            if (pr0 < rend) atomicAdd(&out[g_perm[pr0]], s0);
            if (pr1 < rend) atomicAdd(&out[g_perm[pr1]], s1);
        }
    }
}

// ---------------- launch ----------------
extern "C" void kernel_launch(void* const* d_in, const int* in_sizes, int n_in,
                              void* d_out, int out_size) {
    const float* x         = (const float*)d_in[0];
    const float* intention = (const float*)d_in[1];
    const float* W1        = (const float*)d_in[2];
    const float* b1        = (const float*)d_in[3];
    const float* W2        = (const float*)d_in[4];
    const float* b2        = (const float*)d_in[5];
    const float* W3        = (const float*)d_in[6];
    const float* b3        = (const float*)d_in[7];
    float* out             = (float*)d_out;

    prep_kernel<<<1, 1024>>>(intention, W2, b2, W3, b3, out);
    gemm_kernel<<<dim3(GY, GX), 256>>>(x, W1, b1, W3, out);
}

// round 5
// speedup vs baseline: 3.1174x; 1.1484x over previous
#include <cuda_runtime.h>
#include <cstdint>

// ---------------- problem constants ----------------
#define BATCH 4096
#define DIM   2048
#define NK    8
#define H2    64

// ---------------- tiling ----------------
#define BM     128
#define BN     256
#define KC     32
#define NCHUNK (DIM / KC)        // 64
#define GX     (DIM / BN)        // 8 d-blocks
#define GYT    40                // max m-tiles
#define NSTAGE 3

#define PITCH_B 80               // bytes per smem row (64 data + 16 pad)
#define A_TILE  (BM * PITCH_B)   // 10240
#define B_TILE  (BN * PITCH_B)   // 20480
#define STAGE_B (2 * A_TILE + 2 * B_TILE)   // 61440: Ahi|Alo|Bhi|Blo
#define SMEM_TOTAL (NSTAGE * STAGE_B)       // 184320

// ---------------- device scratch (no allocation allowed) ----------------
__device__ int g_perm[BATCH];
__device__ int g_tile_k[GYT];
__device__ int g_tile_row0[GYT];
__device__ int g_tile_rend[GYT];
__device__ int g_ntiles;
// pre-converted operands (bf16 hi/lo packed as uint4 = 8 elements)
__device__ uint4 g_xhi[BATCH * DIM / 8];          // 16 MB
__device__ uint4 g_xlo[BATCH * DIM / 8];          // 16 MB
__device__ uint4 g_w1hi[(size_t)NK * DIM * DIM / 8];  // 64 MB, regrouped [k][d][j]
__device__ uint4 g_w1lo[(size_t)NK * DIM * DIM / 8];  // 64 MB

// ---------------- PTX helpers ----------------
__device__ __forceinline__ uint32_t smem_u32(const void* p) {
    uint32_t a;
    asm("{ .reg .u64 t; cvta.to.shared.u64 t, %1; cvt.u32.u64 %0, t; }" : "=r"(a) : "l"(p));
    return a;
}

__device__ __forceinline__ void cpasync16(uint32_t dst, const void* src) {
    asm volatile("{ .reg .u64 g; cvta.to.global.u64 g, %1; "
                 "cp.async.cg.shared.global [%0], [g], 16; }"
                 :: "r"(dst), "l"(src) : "memory");
}
#define CP_COMMIT() asm volatile("cp.async.commit_group;" ::: "memory")
#define CP_WAIT1()  asm volatile("cp.async.wait_group 1;" ::: "memory")

__device__ __forceinline__ void ldsm4(uint32_t* r, uint32_t addr) {
    asm volatile("ldmatrix.sync.aligned.m8n8.x4.shared.b16 {%0,%1,%2,%3}, [%4];"
                 : "=r"(r[0]), "=r"(r[1]), "=r"(r[2]), "=r"(r[3]) : "r"(addr));
}

__device__ __forceinline__ void mma_bf16(float* c, const uint32_t* a, const uint32_t* b) {
    asm volatile(
        "mma.sync.aligned.m16n8k16.row.col.f32.bf16.bf16.f32 "
        "{%0,%1,%2,%3}, {%4,%5,%6,%7}, {%8,%9}, {%0,%1,%2,%3};"
        : "+f"(c[0]), "+f"(c[1]), "+f"(c[2]), "+f"(c[3])
        : "r"(a[0]), "r"(a[1]), "r"(a[2]), "r"(a[3]), "r"(b[0]), "r"(b[1]));
}

// pack two fp32 -> bf16x2 (lo_ -> lower half)
__device__ __forceinline__ uint32_t pk_bf16x2(float lo_, float hi_) {
    uint32_t r;
    asm("cvt.rn.bf16x2.f32 %0, %1, %2;" : "=r"(r) : "f"(hi_), "f"(lo_));
    return r;
}

// 8 fp32 -> hi uint4 (truncated top-16 bits) + lo uint4 (residual, rn-bf16)
__device__ __forceinline__ void cvt8(float4 a, float4 b, uint4& hi, uint4& lo) {
    uint32_t ua0 = __float_as_uint(a.x), ua1 = __float_as_uint(a.y);
    uint32_t ua2 = __float_as_uint(a.z), ua3 = __float_as_uint(a.w);
    uint32_t ub0 = __float_as_uint(b.x), ub1 = __float_as_uint(b.y);
    uint32_t ub2 = __float_as_uint(b.z), ub3 = __float_as_uint(b.w);
    hi.x = __byte_perm(ua0, ua1, 0x7632);
    hi.y = __byte_perm(ua2, ua3, 0x7632);
    hi.z = __byte_perm(ub0, ub1, 0x7632);
    hi.w = __byte_perm(ub2, ub3, 0x7632);
    float r0 = a.x - __uint_as_float(ua0 & 0xFFFF0000u);
    float r1 = a.y - __uint_as_float(ua1 & 0xFFFF0000u);
    float r2 = a.z - __uint_as_float(ua2 & 0xFFFF0000u);
    float r3 = a.w - __uint_as_float(ua3 & 0xFFFF0000u);
    float r4 = b.x - __uint_as_float(ub0 & 0xFFFF0000u);
    float r5 = b.y - __uint_as_float(ub1 & 0xFFFF0000u);
    float r6 = b.z - __uint_as_float(ub2 & 0xFFFF0000u);
    float r7 = b.w - __uint_as_float(ub3 & 0xFFFF0000u);
    lo.x = pk_bf16x2(r0, r1);
    lo.y = pk_bf16x2(r2, r3);
    lo.z = pk_bf16x2(r4, r5);
    lo.w = pk_bf16x2(r6, r7);
}

// ---------------- prep: sort by intention, tile table, t2, out init ----------------
__global__ void __launch_bounds__(1024) prep_kernel(
    const float* __restrict__ intention, const float* __restrict__ W2,
    const float* __restrict__ b2, const float* __restrict__ W3,
    const float* __restrict__ b3, float* __restrict__ out) {
    __shared__ int cnt[NK], cur[NK];
    __shared__ float t2s[NK];
    int t = threadIdx.x;
    if (t < NK) cnt[t] = 0;
    __syncthreads();

    int myk[4];
#pragma unroll
    for (int i = 0; i < 4; i++) {
        int b = t + i * 1024;
        const float4* p = (const float4*)(intention + (size_t)b * NK);
        float4 v0 = p[0], v1 = p[1];
        int k = 0;
        if (v0.y > 0.5f) k = 1;
        if (v0.z > 0.5f) k = 2;
        if (v0.w > 0.5f) k = 3;
        if (v1.x > 0.5f) k = 4;
        if (v1.y > 0.5f) k = 5;
        if (v1.z > 0.5f) k = 6;
        if (v1.w > 0.5f) k = 7;
        myk[i] = k;
        atomicAdd(&cnt[k], 1);
    }
    __syncthreads();

    if (t == 0) {
        int off = 0, nt = 0;
        for (int k = 0; k < NK; k++) {
            int c = cnt[k];
            for (int r = 0; r < c; r += BM) {
                g_tile_k[nt] = k;
                g_tile_row0[nt] = off + r;
                g_tile_rend[nt] = off + c;
                nt++;
            }
            cur[k] = off;
            off += c;
        }
        g_ntiles = nt;
    }
    if (t < NK) {
        float s = 0.f;
        for (int h = 0; h < H2; h++) {
            float v = W2[h * NK + t] + b2[h];
            s += fmaxf(v, 0.f) * W3[DIM + h];
        }
        t2s[t] = s;
    }
    __syncthreads();

    float bias = b3[0];
#pragma unroll
    for (int i = 0; i < 4; i++) {
        int b = t + i * 1024;
        int pos = atomicAdd(&cur[myk[i]], 1);
        g_perm[pos] = b;
        out[b] = bias + t2s[myk[i]];
    }
}

// ---------------- pre-pass converters ----------------
__global__ void __launch_bounds__(256) cvt_x_kernel(const float* __restrict__ x) {
    int row = blockIdx.x;          // 0..4095
    int t   = threadIdx.x;         // 8 elements each
    const float4* src = (const float4*)x + (size_t)row * (DIM / 4) + t * 2;
    float4 v0 = src[0], v1 = src[1];
    uint4 hi, lo;
    cvt8(v0, v1, hi, lo);
    size_t idx = (size_t)row * (DIM / 8) + t;
    g_xhi[idx] = hi;
    g_xlo[idx] = lo;
}

__global__ void __launch_bounds__(256) cvt_w_kernel(const float* __restrict__ W1) {
    int r = blockIdx.x;            // 0..16383 (row = d*8+k)
    int t = threadIdx.x;
    int d = r >> 3, k = r & 7;
    const float4* src = (const float4*)W1 + (size_t)r * (DIM / 4) + t * 2;
    float4 v0 = src[0], v1 = src[1];
    uint4 hi, lo;
    cvt8(v0, v1, hi, lo);
    size_t idx = ((size_t)k * DIM + d) * (DIM / 8) + t;   // regroup by branch k
    g_w1hi[idx] = hi;
    g_w1lo[idx] = lo;
}

// ---------------- fused grouped HMMA GEMM (cp.async 3-stage) ----------------
__global__ void __launch_bounds__(256, 1) gemm_kernel(
    const float* __restrict__ b1, const float* __restrict__ W3,
    float* __restrict__ out) {
    int tile = blockIdx.x;
    if (tile >= g_ntiles) return;
    int k     = g_tile_k[tile];
    int row0  = g_tile_row0[tile];
    int rend  = g_tile_rend[tile];
    int dbase = blockIdx.y * BN;

    extern __shared__ char smem[];
    uint32_t sb = smem_u32(smem);
    int t    = threadIdx.x;
    int lane = t & 31;
    int wid  = t >> 5;
    int mw   = wid & 1;            // 2 warp-rows of 64
    int nw   = wid >> 1;           // 4 warp-cols of 64

    // ---- cp.async loader sources (advance +4 uint4 per chunk) ----
    const uint4* asrc_h[2];
    const uint4* asrc_l[2];
    uint32_t adst[2];
#pragma unroll
    for (int j = 0; j < 2; j++) {
        int idx = t + j * 256;             // 0..511
        int ar = idx >> 2, aseg = idx & 3;
        int pr = row0 + ar;
        int samp = (pr < rend) ? g_perm[pr] : g_perm[row0];
        size_t off = (size_t)samp * (DIM / 8) + aseg;
        asrc_h[j] = g_xhi + off;
        asrc_l[j] = g_xlo + off;
        adst[j] = (uint32_t)ar * PITCH_B + (uint32_t)aseg * 16u;
    }
    const uint4* bsrc_h[4];
    const uint4* bsrc_l[4];
    uint32_t bdst[4];
#pragma unroll
    for (int j = 0; j < 4; j++) {
        int idx = t + j * 256;             // 0..1023
        int br = idx >> 2, bseg = idx & 3;
        size_t off = ((size_t)k * DIM + dbase + br) * (DIM / 8) + bseg;
        bsrc_h[j] = g_w1hi + off;
        bsrc_l[j] = g_w1lo + off;
        bdst[j] = (uint32_t)br * PITCH_B + (uint32_t)bseg * 16u;
    }

    // ---- ldmatrix lane base offsets ----
    uint32_t a_base = ((uint32_t)(mw * 64 + (lane & 7) + 8 * ((lane >> 3) & 1))) * PITCH_B
                    + (uint32_t)(lane >> 4) * 16u;
    uint32_t b_base = ((uint32_t)(nw * 64 + (lane & 7) + 8 * ((lane >> 3) >> 1))) * PITCH_B
                    + (uint32_t)((lane >> 3) & 1) * 16u;

    float acc[4][8][4];
#pragma unroll
    for (int i = 0; i < 4; i++)
#pragma unroll
        for (int j = 0; j < 8; j++)
#pragma unroll
            for (int e = 0; e < 4; e++) acc[i][j][e] = 0.f;

    // issue chunk c into stage buffer st
    auto issue = [&](int c, uint32_t st) {
        if (c < NCHUNK) {
            int c4 = c * 4;
#pragma unroll
            for (int j = 0; j < 2; j++) {
                cpasync16(st + adst[j], asrc_h[j] + c4);
                cpasync16(st + A_TILE + adst[j], asrc_l[j] + c4);
            }
#pragma unroll
            for (int j = 0; j < 4; j++) {
                cpasync16(st + 2 * A_TILE + bdst[j], bsrc_h[j] + c4);
                cpasync16(st + 2 * A_TILE + B_TILE + bdst[j], bsrc_l[j] + c4);
            }
        }
        CP_COMMIT();
    };

    issue(0, sb);
    issue(1, sb + STAGE_B);

    int cs = 0;           // compute stage
    int is = 2;           // issue stage (= (c+2) % 3)
#pragma unroll 1
    for (int c = 0; c < NCHUNK; c++) {
        CP_WAIT1();
        __syncthreads();
        issue(c + 2, sb + (uint32_t)is * STAGE_B);
        uint32_t st = sb + (uint32_t)cs * STAGE_B;

#pragma unroll
        for (int ks = 0; ks < 2; ks++) {
            uint32_t ko = (uint32_t)ks * 32u;
            uint32_t Bh[4][4], Bl[4][4];
#pragma unroll
            for (int jp = 0; jp < 4; jp++) {
                ldsm4(Bh[jp], st + 2 * A_TILE + b_base + (uint32_t)jp * (16u * PITCH_B) + ko);
                ldsm4(Bl[jp], st + 2 * A_TILE + B_TILE + b_base + (uint32_t)jp * (16u * PITCH_B) + ko);
            }
#pragma unroll
            for (int i = 0; i < 4; i++) {
                uint32_t Ah[4], Al[4];
                ldsm4(Ah, st + a_base + (uint32_t)i * (16u * PITCH_B) + ko);
                ldsm4(Al, st + A_TILE + a_base + (uint32_t)i * (16u * PITCH_B) + ko);
#pragma unroll
                for (int j = 0; j < 8; j++) {
                    int jp = j >> 1, h = (j & 1) * 2;
                    mma_bf16(acc[i][j], Ah, &Bh[jp][h]);
                    mma_bf16(acc[i][j], Al, &Bh[jp][h]);
                    mma_bf16(acc[i][j], Ah, &Bl[jp][h]);
                }
            }
        }
        cs = (cs == 2) ? 0 : cs + 1;
        is = (is == 2) ? 0 : is + 1;
    }

    // ---- fused epilogue: relu(acc + b1) * W3, row-reduce, atomicAdd ----
    float bb0[8], bb1[8], w30[8], w31[8];
#pragma unroll
    for (int j = 0; j < 8; j++) {
        int d = dbase + nw * 64 + j * 8 + 2 * (lane & 3);
        bb0[j] = __ldg(&b1[(size_t)d * NK + k]);
        bb1[j] = __ldg(&b1[(size_t)(d + 1) * NK + k]);
        w30[j] = __ldg(&W3[d]);
        w31[j] = __ldg(&W3[d + 1]);
    }
#pragma unroll
    for (int i = 0; i < 4; i++) {
        float s0 = 0.f, s1 = 0.f;
#pragma unroll
        for (int j = 0; j < 8; j++) {
            s0 = fmaf(fmaxf(acc[i][j][0] + bb0[j], 0.f), w30[j], s0);
            s0 = fmaf(fmaxf(acc[i][j][1] + bb1[j], 0.f), w31[j], s0);
            s1 = fmaf(fmaxf(acc[i][j][2] + bb0[j], 0.f), w30[j], s1);
            s1 = fmaf(fmaxf(acc[i][j][3] + bb1[j], 0.f), w31[j], s1);
        }
        s0 += __shfl_xor_sync(0xFFFFFFFFu, s0, 1);
        s0 += __shfl_xor_sync(0xFFFFFFFFu, s0, 2);
        s1 += __shfl_xor_sync(0xFFFFFFFFu, s1, 1);
        s1 += __shfl_xor_sync(0xFFFFFFFFu, s1, 2);
        if ((lane & 3) == 0) {
            int m0 = mw * 64 + i * 16 + (lane >> 2);
            int pr0 = row0 + m0;
            int pr1 = pr0 + 8;
            if (pr0 < rend) atomicAdd(&out[g_perm[pr0]], s0);
            if (pr1 < rend) atomicAdd(&out[g_perm[pr1]], s1);
        }
    }
}

// ---------------- launch ----------------
extern "C" void kernel_launch(void* const* d_in, const int* in_sizes, int n_in,
                              void* d_out, int out_size) {
    const float* x         = (const float*)d_in[0];
    const float* intention = (const float*)d_in[1];
    const float* W1        = (const float*)d_in[2];
    const float* b1        = (const float*)d_in[3];
    const float* W2        = (const float*)d_in[4];
    const float* b2        = (const float*)d_in[5];
    const float* W3        = (const float*)d_in[6];
    const float* b3        = (const float*)d_in[7];
    float* out             = (float*)d_out;

    cudaFuncSetAttribute(gemm_kernel, cudaFuncAttributeMaxDynamicSharedMemorySize,
                         SMEM_TOTAL);

    prep_kernel<<<1, 1024>>>(intention, W2, b2, W3, b3, out);
    cvt_x_kernel<<<BATCH, 256>>>(x);
    cvt_w_kernel<<<DIM * NK, 256>>>(W1);
    gemm_kernel<<<dim3(GYT, GX), 256, SMEM_TOTAL>>>(b1, W3, out);
}

// round 6
// speedup vs baseline: 4.4057x; 1.4133x over previous
#include <cuda_runtime.h>
#include <cuda_fp16.h>
#include <cstdint>

// ---------------- problem constants ----------------
#define BATCH 4096
#define DIM   2048
#define NK    8
#define H2    64

// ---------------- tiling ----------------
#define BM     64
#define BN     256
#define KC     32
#define NCHUNK (DIM / KC)        // 64
#define GX     (DIM / BN)        // 8 d-blocks
#define GYT    72                // max m-tiles (worst case 64+8)
#define NSTAGE 3

#define PITCH_B 80               // bytes per smem row (64 data + 16 pad)
#define A_T     (BM * PITCH_B)   // 5120
#define B_T     (BN * PITCH_B)   // 20480
#define STAGE_B (2 * A_T + B_T)  // 30720: Ah | Al | Bh
#define SMEM_TOTAL (NSTAGE * STAGE_B)   // 92160 (x2 CTAs = 184320 <= 227KB/SM)

// ---------------- device scratch (no allocation allowed) ----------------
__device__ int g_perm[BATCH];
__device__ int g_tile_k[GYT];
__device__ int g_tile_row0[GYT];
__device__ int g_tile_rend[GYT];
__device__ int g_ntiles;
// pre-converted operands (fp16 packed as uint4 = 8 elements)
__device__ uint4 g_xh[BATCH * DIM / 8];               // 16.8 MB
__device__ uint4 g_xl[BATCH * DIM / 8];               // 16.8 MB
__device__ uint4 g_wh[(size_t)NK * DIM * DIM / 8];    // 67 MB, regrouped [k][d][j]

// ---------------- PTX helpers ----------------
__device__ __forceinline__ uint32_t smem_u32(const void* p) {
    uint32_t a;
    asm("{ .reg .u64 t; cvta.to.shared.u64 t, %1; cvt.u32.u64 %0, t; }" : "=r"(a) : "l"(p));
    return a;
}

__device__ __forceinline__ void cpasync16(uint32_t dst, const void* src) {
    asm volatile("{ .reg .u64 g; cvta.to.global.u64 g, %1; "
                 "cp.async.cg.shared.global [%0], [g], 16; }"
                 :: "r"(dst), "l"(src) : "memory");
}
#define CP_COMMIT() asm volatile("cp.async.commit_group;" ::: "memory")
#define CP_WAIT1()  asm volatile("cp.async.wait_group 1;" ::: "memory")

__device__ __forceinline__ void ldsm4(uint32_t* r, uint32_t addr) {
    asm volatile("ldmatrix.sync.aligned.m8n8.x4.shared.b16 {%0,%1,%2,%3}, [%4];"
                 : "=r"(r[0]), "=r"(r[1]), "=r"(r[2]), "=r"(r[3]) : "r"(addr));
}

__device__ __forceinline__ void mma_f16(float* c, const uint32_t* a, const uint32_t* b) {
    asm volatile(
        "mma.sync.aligned.m16n8k16.row.col.f32.f16.f16.f32 "
        "{%0,%1,%2,%3}, {%4,%5,%6,%7}, {%8,%9}, {%0,%1,%2,%3};"
        : "+f"(c[0]), "+f"(c[1]), "+f"(c[2]), "+f"(c[3])
        : "r"(a[0]), "r"(a[1]), "r"(a[2]), "r"(a[3]), "r"(b[0]), "r"(b[1]));
}

// pack two fp32 -> fp16x2 with residuals
__device__ __forceinline__ uint32_t packh2r(float f0, float f1, float& r0, float& r1) {
    __half2 p = __floats2half2_rn(f0, f1);
    r0 = f0 - __low2float(p);
    r1 = f1 - __high2float(p);
    return *reinterpret_cast<uint32_t*>(&p);
}
__device__ __forceinline__ uint32_t packh2(float f0, float f1) {
    __half2 p = __floats2half2_rn(f0, f1);
    return *reinterpret_cast<uint32_t*>(&p);
}

// 8 fp32 -> hi uint4 (rn fp16) + lo uint4 (residual, rn fp16)
__device__ __forceinline__ void cvt8h(float4 a, float4 b, uint4& hi, uint4& lo) {
    float r0, r1, r2, r3, r4, r5, r6, r7;
    hi.x = packh2r(a.x, a.y, r0, r1);
    hi.y = packh2r(a.z, a.w, r2, r3);
    hi.z = packh2r(b.x, b.y, r4, r5);
    hi.w = packh2r(b.z, b.w, r6, r7);
    lo.x = packh2(r0, r1);
    lo.y = packh2(r2, r3);
    lo.z = packh2(r4, r5);
    lo.w = packh2(r6, r7);
}

// ---------------- prep: sort by intention, tile table, t2, out init ----------------
__global__ void __launch_bounds__(1024) prep_kernel(
    const float* __restrict__ intention, const float* __restrict__ W2,
    const float* __restrict__ b2, const float* __restrict__ W3,
    const float* __restrict__ b3, float* __restrict__ out) {
    __shared__ int cnt[NK], cur[NK];
    __shared__ float t2s[NK];
    int t = threadIdx.x;
    if (t < NK) cnt[t] = 0;
    __syncthreads();

    int myk[4];
#pragma unroll
    for (int i = 0; i < 4; i++) {
        int b = t + i * 1024;
        const float4* p = (const float4*)(intention + (size_t)b * NK);
        float4 v0 = p[0], v1 = p[1];
        int k = 0;
        if (v0.y > 0.5f) k = 1;
        if (v0.z > 0.5f) k = 2;
        if (v0.w > 0.5f) k = 3;
        if (v1.x > 0.5f) k = 4;
        if (v1.y > 0.5f) k = 5;
        if (v1.z > 0.5f) k = 6;
        if (v1.w > 0.5f) k = 7;
        myk[i] = k;
        atomicAdd(&cnt[k], 1);
    }
    __syncthreads();

    if (t == 0) {
        int off = 0, nt = 0;
        for (int k = 0; k < NK; k++) {
            int c = cnt[k];
            for (int r = 0; r < c; r += BM) {
                g_tile_k[nt] = k;
                g_tile_row0[nt] = off + r;
                g_tile_rend[nt] = off + c;
                nt++;
            }
            cur[k] = off;
            off += c;
        }
        g_ntiles = nt;
    }
    if (t < NK) {
        float s = 0.f;
        for (int h = 0; h < H2; h++) {
            float v = W2[h * NK + t] + b2[h];
            s += fmaxf(v, 0.f) * W3[DIM + h];
        }
        t2s[t] = s;
    }
    __syncthreads();

    float bias = b3[0];
#pragma unroll
    for (int i = 0; i < 4; i++) {
        int b = t + i * 1024;
        int pos = atomicAdd(&cur[myk[i]], 1);
        g_perm[pos] = b;
        out[b] = bias + t2s[myk[i]];
    }
}

// ---------------- pre-pass converters ----------------
__global__ void __launch_bounds__(256) cvt_x_kernel(const float* __restrict__ x) {
    int row = blockIdx.x;
    int t   = threadIdx.x;
    const float4* src = (const float4*)x + (size_t)row * (DIM / 4) + t * 2;
    float4 v0 = src[0], v1 = src[1];
    uint4 hi, lo;
    cvt8h(v0, v1, hi, lo);
    size_t idx = (size_t)row * (DIM / 8) + t;
    g_xh[idx] = hi;
    g_xl[idx] = lo;
}

__global__ void __launch_bounds__(256) cvt_w_kernel(const float* __restrict__ W1) {
    int r = blockIdx.x;            // row = d*8+k
    int t = threadIdx.x;
    int d = r >> 3, k = r & 7;
    const float4* src = (const float4*)W1 + (size_t)r * (DIM / 4) + t * 2;
    float4 v0 = src[0], v1 = src[1];
    uint4 h;
    h.x = packh2(v0.x, v0.y);
    h.y = packh2(v0.z, v0.w);
    h.z = packh2(v1.x, v1.y);
    h.w = packh2(v1.z, v1.w);
    g_wh[((size_t)k * DIM + d) * (DIM / 8) + t] = h;   // regroup by branch k
}

// ---------------- fused grouped HMMA GEMM (fp16 2-product, cp.async 3-stage) ----------------
__global__ void __launch_bounds__(256, 2) gemm_kernel(
    const float* __restrict__ b1, const float* __restrict__ W3,
    float* __restrict__ out) {
    int tile = blockIdx.x;
    if (tile >= g_ntiles) return;
    int k     = g_tile_k[tile];
    int row0  = g_tile_row0[tile];
    int rend  = g_tile_rend[tile];
    int dbase = blockIdx.y * BN;

    extern __shared__ char smem[];
    uint32_t sb = smem_u32(smem);
    int t    = threadIdx.x;
    int lane = t & 31;
    int wid  = t >> 5;
    int mw   = wid & 1;            // 2 warp-rows of 32
    int nw   = wid >> 1;           // 4 warp-cols of 64

    // ---- A loader: 4 threads per row, 1 x 16B seg each (hi + lo) ----
    int ar = t >> 2, aseg = t & 3;
    int pr = row0 + ar;
    int samp = (pr < rend) ? g_perm[pr] : g_perm[row0];
    const uint4* ah = g_xh + (size_t)samp * (DIM / 8) + aseg;
    const uint4* al = g_xl + (size_t)samp * (DIM / 8) + aseg;
    uint32_t adst = (uint32_t)ar * PITCH_B + (uint32_t)aseg * 16u;

    // ---- B loader: 4 transfers per thread ----
    const uint4* bw = g_wh + ((size_t)k * DIM + dbase) * (DIM / 8);
    uint32_t boff[4], bdst[4];
#pragma unroll
    for (int j = 0; j < 4; j++) {
        int idx = t + j * 256;
        int br = idx >> 2, bs = idx & 3;
        boff[j] = (uint32_t)br * (DIM / 8) + (uint32_t)bs;
        bdst[j] = (uint32_t)br * PITCH_B + (uint32_t)bs * 16u;
    }

    // ---- ldmatrix lane base offsets ----
    uint32_t a_base = ((uint32_t)(mw * 32 + (lane & 7) + 8 * ((lane >> 3) & 1))) * PITCH_B
                    + (uint32_t)(lane >> 4) * 16u;
    uint32_t b_base = ((uint32_t)(nw * 64 + (lane & 7) + 8 * ((lane >> 3) >> 1))) * PITCH_B
                    + (uint32_t)((lane >> 3) & 1) * 16u;

    float acc[2][8][4];
#pragma unroll
    for (int i = 0; i < 2; i++)
#pragma unroll
        for (int j = 0; j < 8; j++)
#pragma unroll
            for (int e = 0; e < 4; e++) acc[i][j][e] = 0.f;

    auto issue = [&](int c, uint32_t st) {
        if (c < NCHUNK) {
            uint32_t c4 = (uint32_t)c * 4u;
            cpasync16(st + adst, ah + c4);
            cpasync16(st + A_T + adst, al + c4);
#pragma unroll
            for (int j = 0; j < 4; j++)
                cpasync16(st + 2 * A_T + bdst[j], bw + boff[j] + c4);
        }
        CP_COMMIT();
    };

    issue(0, sb);
    issue(1, sb + STAGE_B);

    int cs = 0, is = 2;
#pragma unroll 1
    for (int c = 0; c < NCHUNK; c++) {
        CP_WAIT1();
        __syncthreads();
        issue(c + 2, sb + (uint32_t)is * STAGE_B);
        uint32_t st = sb + (uint32_t)cs * STAGE_B;

#pragma unroll
        for (int ks = 0; ks < 2; ks++) {
            uint32_t ko = (uint32_t)ks * 32u;
            uint32_t Ah[2][4], Al[2][4];
#pragma unroll
            for (int i = 0; i < 2; i++) {
                ldsm4(Ah[i], st + a_base + (uint32_t)i * (16u * PITCH_B) + ko);
                ldsm4(Al[i], st + A_T + a_base + (uint32_t)i * (16u * PITCH_B) + ko);
            }
#pragma unroll
            for (int jp = 0; jp < 4; jp++) {
                uint32_t B[4];
                ldsm4(B, st + 2 * A_T + b_base + (uint32_t)jp * (16u * PITCH_B) + ko);
#pragma unroll
                for (int i = 0; i < 2; i++) {
                    mma_f16(acc[i][jp * 2],     Ah[i], &B[0]);
                    mma_f16(acc[i][jp * 2],     Al[i], &B[0]);
                    mma_f16(acc[i][jp * 2 + 1], Ah[i], &B[2]);
                    mma_f16(acc[i][jp * 2 + 1], Al[i], &B[2]);
                }
            }
        }
        cs = (cs == 2) ? 0 : cs + 1;
        is = (is == 2) ? 0 : is + 1;
    }

    // ---- fused epilogue: relu(acc + b1) * W3, row-reduce, atomicAdd ----
#pragma unroll
    for (int i = 0; i < 2; i++) {
        float s0 = 0.f, s1 = 0.f;
#pragma unroll
        for (int j = 0; j < 8; j++) {
            int d = dbase + nw * 64 + j * 8 + 2 * (lane & 3);
            float bb0 = __ldg(&b1[(size_t)d * NK + k]);
            float bb1 = __ldg(&b1[(size_t)(d + 1) * NK + k]);
            float w30 = __ldg(&W3[d]);
            float w31 = __ldg(&W3[d + 1]);
            s0 = fmaf(fmaxf(acc[i][j][0] + bb0, 0.f), w30, s0);
            s0 = fmaf(fmaxf(acc[i][j][1] + bb1, 0.f), w31, s0);
            s1 = fmaf(fmaxf(acc[i][j][2] + bb0, 0.f), w30, s1);
            s1 = fmaf(fmaxf(acc[i][j][3] + bb1, 0.f), w31, s1);
        }
        s0 += __shfl_xor_sync(0xFFFFFFFFu, s0, 1);
        s0 += __shfl_xor_sync(0xFFFFFFFFu, s0, 2);
        s1 += __shfl_xor_sync(0xFFFFFFFFu, s1, 1);
        s1 += __shfl_xor_sync(0xFFFFFFFFu, s1, 2);
        if ((lane & 3) == 0) {
            int m0 = mw * 32 + i * 16 + (lane >> 2);
            int pr0 = row0 + m0;
            int pr1 = pr0 + 8;
            if (pr0 < rend) atomicAdd(&out[g_perm[pr0]], s0);
            if (pr1 < rend) atomicAdd(&out[g_perm[pr1]], s1);
        }
    }
}

// ---------------- launch ----------------
extern "C" void kernel_launch(void* const* d_in, const int* in_sizes, int n_in,
                              void* d_out, int out_size) {
    const float* x         = (const float*)d_in[0];
    const float* intention = (const float*)d_in[1];
    const float* W1        = (const float*)d_in[2];
    const float* b1        = (const float*)d_in[3];
    const float* W2        = (const float*)d_in[4];
    const float* b2        = (const float*)d_in[5];
    const float* W3        = (const float*)d_in[6];
    const float* b3        = (const float*)d_in[7];
    float* out             = (float*)d_out;

    cudaFuncSetAttribute(gemm_kernel, cudaFuncAttributeMaxDynamicSharedMemorySize,
                         SMEM_TOTAL);

    prep_kernel<<<1, 1024>>>(intention, W2, b2, W3, b3, out);
    cvt_x_kernel<<<BATCH, 256>>>(x);
    cvt_w_kernel<<<DIM * NK, 256>>>(W1);
    gemm_kernel<<<dim3(GYT, GX), 256, SMEM_TOTAL>>>(b1, W3, out);
}